// round 14
// baseline (speedup 1.0000x reference)
#include <cuda_runtime.h>
#include <cstdint>

#define B_    128
#define NPG   12
#define EPG   132
#define E_TOT 16896
#define NT    1536
#define CAP   88
typedef unsigned long long ull;

__device__ float d_Wt[131072];         // tf32-prerounded, fragment-swizzled
__device__ float d_fc[E_TOT * 1024];   // slot-compacted per graph: (g*132+slot)*1024
__device__ float d_fv[E_TOT * 256];    // slot-indexed
__device__ float d_uv[E_TOT * 256];
__device__ int   d_np[B_];
__device__ int   d_actL[B_ * EPG];

__device__ __forceinline__ ull pk2(float lo, float hi) {
    ull r;
    asm("mov.b64 %0, {%1, %2};" : "=l"(r) : "f"(lo), "f"(hi));
    return r;
}
__device__ __forceinline__ void fma2(ull& d, ull a, ull b) {
    asm("fma.rn.f32x2 %0, %1, %2, %0;" : "+l"(d) : "l"(a), "l"(b));
}
__device__ __forceinline__ void up2(ull v, float& lo, float& hi) {
    asm("mov.b64 {%0, %1}, %2;" : "=f"(lo), "=f"(hi) : "l"(v));
}
__device__ __forceinline__ int revloc(int ee) {
    int s = ee / 11, dd = ee - s * 11;
    int d = dd + (dd >= s);
    return d * 11 + s - (s > d);
}
__device__ __forceinline__ void mma_tf32(float* d, const uint32_t* a, uint32_t b0, uint32_t b1) {
    asm volatile("mma.sync.aligned.m16n8k8.row.col.f32.tf32.tf32.f32 "
        "{%0,%1,%2,%3}, {%4,%5,%6,%7}, {%8,%9}, {%0,%1,%2,%3};\n"
        : "+f"(d[0]), "+f"(d[1]), "+f"(d[2]), "+f"(d[3])
        : "r"(a[0]), "r"(a[1]), "r"(a[2]), "r"(a[3]), "r"(b0), "r"(b1));
}
__device__ __forceinline__ uint32_t to_tf32(float v) {
    uint32_t r;
    asm("cvt.rna.tf32.f32 %0, %1;" : "=r"(r) : "f"(v));
    return r;
}
__device__ __forceinline__ void split_tf32(float v, uint32_t& hi, uint32_t& lo) {
    hi = to_tf32(v);
    lo = to_tf32(v - __uint_as_float(hi));
}

// ---- K1: Wt pack only — coalesced loads, scattered stores ----
__global__ void __launch_bounds__(256) prep_k(const float* __restrict__ Wjf,
                                              const float* __restrict__ Wju) {
    int i = blockIdx.x * 256 + threadIdx.x;     // 131072
    int k = i >> 10, j = i & 1023;
    float v = (j < 512) ? Wjf[k * 512 + j] : Wju[k * 512 + j - 512];
    int nt = j >> 7, wn = (j >> 6) & 1, f = (j >> 3) & 7, hi = j & 7;
    int ks = k >> 3, r = (k >> 2) & 1, la = k & 3;
    int lane = hi * 4 + la;
    int dest = (nt << 14) | (ks << 10) | (wn << 9) | (lane << 4) | (f << 1) | r;
    d_Wt[dest] = __uint_as_float(to_tf32(v));
}

// ---- K2: front kernel — gc + flv + flag + gemm + einsum (1024 thr, one CTA/graph) ----
// smem floats: s_ef 0 (17424) | s_W 17424 (4096) | s_fl 21520 (4224) | s_Wc 25744 (64)
//              | s_gc 25808 (1056) | s_gf 26864 (64) | s_act 26928 (132i) | s_np
#define FRONT_SMEM (27062 * 4)
__global__ void __launch_bounds__(1024, 1) front_k(
        const float* __restrict__ ef, const float* __restrict__ Wfl,
        const float* __restrict__ noise, const float* __restrict__ Wc,
        const float* __restrict__ bc,
        const float* __restrict__ Wjf, const float* __restrict__ bjf,
        const float* __restrict__ Wju, const float* __restrict__ bju,
        const float* __restrict__ bfl, const float* __restrict__ gf) {
    extern __shared__ __align__(16) float sm[];
    float* s_ef = sm;
    float* s_W  = sm + 17424;
    float* s_fl = sm + 21520;
    float* s_Wc = sm + 25744;
    float* s_gc = sm + 25808;
    float* s_gf = sm + 26864;
    int* s_act = (int*)(sm + 26928);
    int* s_np  = (int*)(sm + 27060);

    int g = blockIdx.x, t = threadIdx.x;
    if (t == 0) *s_np = 0;
    for (int i = t; i < 4224; i += 1024) {
        int r = i >> 5, q = i & 31;
        float4 v = *(const float4*)(ef + (g * EPG + r) * 128 + q * 4);
        *(float4*)(s_ef + r * 132 + q * 4) = v;
    }
    if (t < 1024) *(float4*)(s_W + t * 4) = *(const float4*)(Wfl + t * 4);
    if (t >= 1024 - 64) { /* nothing */ }
    if (t < 64) { s_Wc[t] = Wc[t]; s_gf[t] = gf[g * 64 + t]; }
    __syncthreads();

    // gc: per-graph part + bias for all 1056 cols
    for (int j = t; j < 1056; j += 1024) {
        const float* Wp; int st; float acc;
        if (j < 512)        { Wp = Wjf + 128 * 512 + j;          st = 512; acc = bjf[j]; }
        else if (j < 1024)  { Wp = Wju + 128 * 512 + (j - 512);  st = 512; acc = bju[j - 512]; }
        else                { Wp = Wfl + 128 * 32  + (j - 1024); st = 32;  acc = bfl[j - 1024]; }
#pragma unroll 8
        for (int k = 0; k < 64; ++k) acc += s_gf[k] * Wp[k * st];
        s_gc[j] = acc;
    }
    __syncthreads();

    // fl linear: 528 threads, 8 cols each
    if (t < 528) {
        int e = t >> 2, co = (t & 3) * 8;
        ull acc[4];
        const float* gb = s_gc + 1024 + co;
#pragma unroll
        for (int c = 0; c < 4; ++c) acc[c] = pk2(gb[c * 2], gb[c * 2 + 1]);
        const float* er = s_ef + e * 132;
#pragma unroll 4
        for (int k = 0; k < 128; ++k) {
            float a = er[k];
            ull aa = pk2(a, a);
            const float4* wr = (const float4*)(s_W + k * 32 + co);
            float4 w0 = wr[0], w1 = wr[1];
            fma2(acc[0], aa, pk2(w0.x, w0.y)); fma2(acc[1], aa, pk2(w0.z, w0.w));
            fma2(acc[2], aa, pk2(w1.x, w1.y)); fma2(acc[3], aa, pk2(w1.z, w1.w));
        }
        float* op = s_fl + e * 32 + co;
#pragma unroll
        for (int c = 0; c < 4; ++c) {
            float lo, hi;
            up2(acc[c], lo, hi);
            op[c * 2] = lo; op[c * 2 + 1] = hi;
        }
    }
    __syncthreads();

    // gumbel flags + pair-ordered active list
    if (t < EPG) {
        int e = t, rev = revloc(e);
        const float* pe = s_fl + e * 32;
        const float* pr = s_fl + rev * 32;
        float l0 = bc[0], l1 = bc[1];
#pragma unroll 8
        for (int c = 0; c < 32; ++c) {
            float p = pe[c] * pr[c];
            l0 += p * s_Wc[c * 2];
            l1 += p * s_Wc[c * 2 + 1];
        }
        int ge = g * EPG + e, grev = g * EPG + rev;
        int mn = min(ge, grev);
        float y0 = l0 + noise[2 * mn];
        float y1 = l1 + noise[2 * mn + 1];
        if (y0 >= y1 && e < rev) {
            int q = atomicAdd(s_np, 1);
            s_act[2 * q] = e;
            s_act[2 * q + 1] = rev;
        }
    }
    __syncthreads();
    int npairs = *s_np;
    int cnt = npairs * 2;
    if (t == 0) d_np[g] = npairs;
    if (t < cnt) d_actL[g * EPG + t] = s_act[t];

    // tf32 GEMM: 32 warps, warp = (nt<<2)|(wn<<1)|mh -> 16 rows x 64 cols
    {
        int lane = t & 31, warp = t >> 5;
        int nt = warp >> 2, wn = (warp >> 1) & 1, mh = warp & 1;
        int nM = (cnt + 31) >> 5;
        float* fcg = d_fc + (size_t)(g * 132) * 1024;
        int la = lane & 3;
        const float4* wt = (const float4*)d_Wt + (((nt * 16) * 2 + wn) * 32 + lane) * 4;
        for (int mc = 0; mc < nM; ++mc) {
            float acc[8][4];
#pragma unroll
            for (int f = 0; f < 8; ++f)
#pragma unroll
                for (int j = 0; j < 4; ++j) acc[f][j] = 0.f;
            int rb = mc * 32 + mh * 16 + (lane >> 2);
            int c1 = cnt - 1;
            const float* A0 = s_ef + s_act[min(rb, c1)] * 132 + la;
            const float* A1 = s_ef + s_act[min(rb + 8, c1)] * 132 + la;
#pragma unroll
            for (int ks = 0; ks < 16; ++ks) {
                const float4* wp = wt + ks * 256;
                float4 b0 = wp[0], b1 = wp[1], b2 = wp[2], b3 = wp[3];
                uint32_t a[4];
                a[0] = to_tf32(A0[ks * 8]);     a[1] = to_tf32(A1[ks * 8]);
                a[2] = to_tf32(A0[ks * 8 + 4]); a[3] = to_tf32(A1[ks * 8 + 4]);
                mma_tf32(acc[0], a, __float_as_uint(b0.x), __float_as_uint(b0.y));
                mma_tf32(acc[1], a, __float_as_uint(b0.z), __float_as_uint(b0.w));
                mma_tf32(acc[2], a, __float_as_uint(b1.x), __float_as_uint(b1.y));
                mma_tf32(acc[3], a, __float_as_uint(b1.z), __float_as_uint(b1.w));
                mma_tf32(acc[4], a, __float_as_uint(b2.x), __float_as_uint(b2.y));
                mma_tf32(acc[5], a, __float_as_uint(b2.z), __float_as_uint(b2.w));
                mma_tf32(acc[6], a, __float_as_uint(b3.x), __float_as_uint(b3.y));
                mma_tf32(acc[7], a, __float_as_uint(b3.z), __float_as_uint(b3.w));
            }
            int gr = lane >> 2, qc = la * 2;
#pragma unroll
            for (int rr = 0; rr < 2; ++rr) {
                int slot = mc * 32 + mh * 16 + gr + rr * 8;
                if (slot < cnt) {
                    float* fcb = fcg + slot * 1024;
#pragma unroll
                    for (int f = 0; f < 8; ++f) {
                        int col = nt * 128 + wn * 64 + f * 8 + qc;
                        float2 gv = *(const float2*)(s_gc + col);
                        float2 ov;
                        ov.x = acc[f][rr * 2 + 0] + gv.x;
                        ov.y = acc[f][rr * 2 + 1] + gv.y;
                        *(float2*)(fcb + col) = ov;
                    }
                }
            }
        }
    }
    __syncthreads();

    // 3xTF32 einsum per pair -> raw fv/uv to gmem (slot-indexed)
    {
        int lane = t & 31, warp = t >> 5;
        int r = lane >> 2, cb = lane & 3;
        const float* fcg = d_fc + (size_t)(g * 132) * 1024;
        float* fvg = d_fv + (size_t)(g * 132) * 256;
        float* uvg = d_uv + (size_t)(g * 132) * 256;
        for (int p = warp; p < npairs; p += 32) {
            const float* fe = fcg + (2 * p) * 1024;
            const float* frp = fcg + (2 * p + 1) * 1024;
#pragma unroll
            for (int mat = 0; mat < 2; ++mat) {
                float acc[2][4];
#pragma unroll
                for (int nf = 0; nf < 2; ++nf)
#pragma unroll
                    for (int j = 0; j < 4; ++j) acc[nf][j] = 0.f;
#pragma unroll
                for (int ks = 0; ks < 4; ++ks) {
                    const float* ap = fe + mat * 512 + r * 32 + ks * 8 + cb;
                    float av[4] = {ap[0], ap[256], ap[4], ap[260]};
                    uint32_t ah[4], al[4];
#pragma unroll
                    for (int j = 0; j < 4; ++j) split_tf32(av[j], ah[j], al[j]);
#pragma unroll
                    for (int nf = 0; nf < 2; ++nf) {
                        const float* bp_ = frp + mat * 512 + (nf * 8 + r) * 32 + ks * 8 + cb;
                        float b0f = bp_[0], b1f = bp_[4];
                        uint32_t bh0, bl0, bh1, bl1;
                        split_tf32(b0f, bh0, bl0);
                        split_tf32(b1f, bh1, bl1);
                        mma_tf32(acc[nf], ah, bh0, bh1);
                        mma_tf32(acc[nf], ah, bl0, bl1);
                        mma_tf32(acc[nf], al, bh0, bh1);
                    }
                }
                float* gme = (mat ? uvg : fvg);
                int se = 2 * p, sr = 2 * p + 1;
#pragma unroll
                for (int nf = 0; nf < 2; ++nf) {
                    int b = nf * 8 + cb * 2;
                    int r8 = r + 8;
                    float* gp = gme + se * 256;
                    gp[r * 16 + b] = acc[nf][0];
                    gp[r * 16 + b + 1] = acc[nf][1];
                    gp[r8 * 16 + b] = acc[nf][2];
                    gp[r8 * 16 + b + 1] = acc[nf][3];
                    float* gq = gme + sr * 256;
                    gq[b * 16 + r] = acc[nf][0];
                    gq[(b + 1) * 16 + r] = acc[nf][1];
                    gq[b * 16 + r8] = acc[nf][2];
                    gq[(b + 1) * 16 + r8] = acc[nf][3];
                }
            }
        }
    }
}

// ---- K3: BP kernel — 1024 threads; node linears fused; factored-exp iterations ----
#define BP_SMEM (56928 * 4)
__global__ void __launch_bounds__(1024, 1) bp_k(
        const float* __restrict__ nf, const float* __restrict__ gf,
        const float* __restrict__ Wif, const float* __restrict__ bif,
        const float* __restrict__ Wiu, const float* __restrict__ biu,
        float* __restrict__ out) {
    extern __shared__ __align__(16) float sm[];
    float* s_dat  = sm;                 // CAP*512; first 1536 aliased as xn during init
    float* nm     = sm + 45056;
    float* nu     = sm + 47168;
    float* s_eagg = sm + 49280;
    float* s_q    = sm + 51392;
    float* s_mxfv = sm + 53504;
    float* s_mm   = sm + 55616;
    float* s_um   = sm + 55808;
    float* s_if   = sm + 56000;
    float* s_iu   = sm + 56192;
    float* s_mxagg = sm + 56384;
    int* s_act  = (int*)(sm + 56516);
    int* s_src  = (int*)(sm + 56648);
    int* s_nl   = (int*)(sm + 56780);
    int* s_ncnt = (int*)(sm + 56912);

    int g = blockIdx.x, t = threadIdx.x;
    int npairs = d_np[g];
    int cnt = npairs * 2;
    int cnt16 = cnt * 16;
    float* xn = s_dat;   // alias: [12][128]
    for (int i = t; i < 4224; i += 1024) nm[i] = 0.f;   // nm+nu contiguous
    for (int i = t; i < 1536; i += 1024) {
        int node = i >> 7, kk = i & 127;
        xn[node * 128 + kk] = (kk < 64) ? nf[(g * NPG + node) * 64 + kk]
                                        : gf[g * 64 + kk - 64];
    }
    if (t < cnt) {
        int e = d_actL[g * EPG + t];
        s_act[t] = e;
        s_src[t] = e / 11;
    }
    __syncthreads();
    // node linears: 384 threads (12 nodes x 32)
    if (t < 384) {
        int node = t >> 5, lane = t & 31;
        int col = lane & 15;
        const float* W = (lane < 16) ? Wif : Wiu;
        float acc = (lane < 16) ? bif[col] : biu[col];
        const float* xr = xn + node * 128;
#pragma unroll 8
        for (int k = 0; k < 128; ++k) acc += xr[k] * W[k * 16 + col];
        int o = node * 16 + col;
        if (lane < 16) { s_if[o] = acc; s_mm[o] = acc; }
        else           { s_iu[o] = acc; s_um[o] = acc; }
    }
    if (t >= 512 && t < 524) {
        int n = t - 512, c = 0;
        for (int p = 0; p < cnt; ++p) {
            int e = s_act[p];
            int s2 = e / 11, dd = e - s2 * 11;
            int d = dd + (dd >= s2);
            if (d == n) s_nl[n * 11 + c++] = p;
        }
        s_ncnt[n] = c;
    }
    __syncthreads();

    // gather + exp-transform: efv = exp(fv - mxfv), uvefv = uv * efv
    float* fvg = d_fv + (size_t)(g * 132) * 256;
    float* uvg = d_uv + (size_t)(g * 132) * 256;
    for (int i = t; i < cnt16; i += 1024) {
        int p = i >> 4, a = i & 15;
        const float* fb = fvg + p * 256 + a * 16;
        const float* ub = uvg + p * 256 + a * 16;
        float4 f[4], u[4];
#pragma unroll
        for (int q = 0; q < 4; ++q) { f[q] = *(const float4*)(fb + q * 4); u[q] = *(const float4*)(ub + q * 4); }
        float mx = fmaxf(fmaxf(fmaxf(f[0].x, f[0].y), fmaxf(f[0].z, f[0].w)),
                   fmaxf(fmaxf(fmaxf(f[1].x, f[1].y), fmaxf(f[1].z, f[1].w)),
                   fmaxf(fmaxf(fmaxf(f[2].x, f[2].y), fmaxf(f[2].z, f[2].w)),
                         fmaxf(fmaxf(f[3].x, f[3].y), fmaxf(f[3].z, f[3].w)))));
        s_mxfv[i] = mx;
#pragma unroll
        for (int q = 0; q < 4; ++q) {
            f[q].x = __expf(f[q].x - mx); f[q].y = __expf(f[q].y - mx);
            f[q].z = __expf(f[q].z - mx); f[q].w = __expf(f[q].w - mx);
            u[q].x *= f[q].x; u[q].y *= f[q].y; u[q].z *= f[q].z; u[q].w *= f[q].w;
        }
        if (p < CAP) {
            float* db = s_dat + p * 512;
            int ax4 = a * 4, ash = a >> 2;
#pragma unroll
            for (int q = 0; q < 4; ++q) {
                *(float4*)(db + (ax4 + (q ^ ash)) * 4) = f[q];
                *(float4*)(db + 256 + (ax4 + (q ^ ash)) * 4) = u[q];
            }
        } else {
            float* fo = fvg + p * 256 + a * 16;
            float* uo = uvg + p * 256 + a * 16;
#pragma unroll
            for (int q = 0; q < 4; ++q) {
                *(float4*)(fo + q * 4) = f[q];
                *(float4*)(uo + q * 4) = u[q];
            }
        }
    }
    __syncthreads();

    for (int it = 0; it < NPG; ++it) {
        // A: per (slot p, b): eagg, q, mxagg
        for (int i = t; i < cnt16; i += 1024) {
            int p = i >> 4, b = i & 15;
            unsigned mask = (t & 16) ? 0xFFFF0000u : 0x0000FFFFu;
            int src = s_src[p];
            int pr = p ^ 1;
            float agg  = s_mm[src * 16 + b] - nm[pr * 16 + b];
            float util = s_um[src * 16 + b] - nu[pr * 16 + b];
            float mxa = agg;
#pragma unroll
            for (int w = 8; w > 0; w >>= 1) mxa = fmaxf(mxa, __shfl_xor_sync(mask, mxa, w));
            float ea = __expf(agg - mxa);
            s_eagg[i] = ea;
            s_q[i] = util * ea;
            if (b == 0) s_mxagg[p] = mxa;
        }
        __syncthreads();
        // B: per (slot p, a): packed-f32x2 dots + log
        for (int i = t; i < cnt16; i += 1024) {
            int p = i >> 4, a = i & 15;
            unsigned mask = (t & 16) ? 0xFFFF0000u : 0x0000FFFFu;
            ull a1 = 0, a2 = 0, a3 = 0;
            const ulonglong2* gp = (const ulonglong2*)(s_eagg + p * 16);
            const ulonglong2* qp = (const ulonglong2*)(s_q + p * 16);
            if (p < CAP) {
                const float* db = s_dat + p * 512;
                int ax4 = a * 4, ash = a >> 2;
#pragma unroll
                for (int qc = 0; qc < 4; ++qc) {
                    ulonglong2 E = *(const ulonglong2*)(db + (ax4 + (qc ^ ash)) * 4);
                    ulonglong2 V = *(const ulonglong2*)(db + 256 + (ax4 + (qc ^ ash)) * 4);
                    ulonglong2 G = gp[qc];
                    ulonglong2 Q = qp[qc];
                    fma2(a1, E.x, G.x); fma2(a1, E.y, G.y);
                    fma2(a2, V.x, G.x); fma2(a2, V.y, G.y);
                    fma2(a3, E.x, Q.x); fma2(a3, E.y, Q.y);
                }
            } else {
                const float* fb = fvg + p * 256 + a * 16;
                const float* ub = uvg + p * 256 + a * 16;
#pragma unroll
                for (int qc = 0; qc < 4; ++qc) {
                    ulonglong2 E = *(const ulonglong2*)(fb + qc * 4);
                    ulonglong2 V = *(const ulonglong2*)(ub + qc * 4);
                    ulonglong2 G = gp[qc];
                    ulonglong2 Q = qp[qc];
                    fma2(a1, E.x, G.x); fma2(a1, E.y, G.y);
                    fma2(a2, V.x, G.x); fma2(a2, V.y, G.y);
                    fma2(a3, E.x, Q.x); fma2(a3, E.y, Q.y);
                }
            }
            float lo, hi;
            up2(a1, lo, hi); float dot1 = lo + hi;
            up2(a2, lo, hi); float dot2 = lo + hi;
            up2(a3, lo, hi); float dot3 = lo + hi;
            float lse = s_mxagg[p] + s_mxfv[i] + __logf(dot1);
            float ssum = lse;
#pragma unroll
            for (int w = 8; w > 0; w >>= 1) ssum += __shfl_xor_sync(mask, ssum, w);
            nm[i] = lse - ssum * 0.0625f;
            nu[i] = (dot2 + dot3) * __fdividef(1.f, dot1);
        }
        __syncthreads();
        // node aggregation
        if (t < 192) {
            int n = t >> 4, b = t & 15;
            float am = 0.f, au = 0.f;
            int nc = s_ncnt[n];
            for (int k = 0; k < nc; ++k) {
                int p = s_nl[n * 11 + k];
                am += nm[p * 16 + b];
                au += nu[p * 16 + b];
            }
            s_mm[t] = am + s_if[t];
            s_um[t] = au + s_iu[t];
        }
        __syncthreads();
    }
    if (t < 16) out[g * 16 + t] = s_um[t];
}

extern "C" void kernel_launch(void* const* d_in, const int* in_sizes, int n_in,
                              void* d_out, int out_size) {
    const float* ef   = (const float*)d_in[0];
    const float* nf   = (const float*)d_in[1];
    const float* gf   = (const float*)d_in[2];
    const float* gn   = (const float*)d_in[7];
    const float* Wjf  = (const float*)d_in[8];
    const float* bjf  = (const float*)d_in[9];
    const float* Wif  = (const float*)d_in[10];
    const float* bif  = (const float*)d_in[11];
    const float* Wju  = (const float*)d_in[12];
    const float* bju  = (const float*)d_in[13];
    const float* Wiu  = (const float*)d_in[14];
    const float* biu  = (const float*)d_in[15];
    const float* Wfl  = (const float*)d_in[16];
    const float* bfl  = (const float*)d_in[17];
    const float* Wcls = (const float*)d_in[18];
    const float* bcls = (const float*)d_in[19];
    float* out = (float*)d_out;

    static int attr_set = 0;
    if (!attr_set) {
        cudaFuncSetAttribute(front_k, cudaFuncAttributeMaxDynamicSharedMemorySize, FRONT_SMEM);
        cudaFuncSetAttribute(bp_k, cudaFuncAttributeMaxDynamicSharedMemorySize, BP_SMEM);
        attr_set = 1;
    }

    prep_k<<<512, 256>>>(Wjf, Wju);
    front_k<<<B_, 1024, FRONT_SMEM>>>(ef, Wfl, gn, Wcls, bcls, Wjf, bjf, Wju, bju, bfl, gf);
    bp_k<<<B_, 1024, BP_SMEM>>>(nf, gf, Wif, bif, Wiu, biu, out);
}

// round 15
// speedup vs baseline: 1.1051x; 1.1051x over previous
#include <cuda_runtime.h>
#include <cstdint>

#define B_    128
#define NPG   12
#define EPG   132
#define E_TOT 16896
#define CAP   90
typedef unsigned long long ull;

__device__ float d_Wt[131072];         // tf32-prerounded, fragment-swizzled
__device__ float d_fc[E_TOT * 1024];   // slot-compacted per graph
__device__ float d_fv[E_TOT * 256];    // spill only (slot-indexed)
__device__ float d_uv[E_TOT * 256];

__device__ __forceinline__ ull pk2(float lo, float hi) {
    ull r;
    asm("mov.b64 %0, {%1, %2};" : "=l"(r) : "f"(lo), "f"(hi));
    return r;
}
__device__ __forceinline__ void fma2(ull& d, ull a, ull b) {
    asm("fma.rn.f32x2 %0, %1, %2, %0;" : "+l"(d) : "l"(a), "l"(b));
}
__device__ __forceinline__ void up2(ull v, float& lo, float& hi) {
    asm("mov.b64 {%0, %1}, %2;" : "=f"(lo), "=f"(hi) : "l"(v));
}
__device__ __forceinline__ int revloc(int ee) {
    int s = ee / 11, dd = ee - s * 11;
    int d = dd + (dd >= s);
    return d * 11 + s - (s > d);
}
__device__ __forceinline__ void mma_tf32(float* d, const uint32_t* a, uint32_t b0, uint32_t b1) {
    asm volatile("mma.sync.aligned.m16n8k8.row.col.f32.tf32.tf32.f32 "
        "{%0,%1,%2,%3}, {%4,%5,%6,%7}, {%8,%9}, {%0,%1,%2,%3};\n"
        : "+f"(d[0]), "+f"(d[1]), "+f"(d[2]), "+f"(d[3])
        : "r"(a[0]), "r"(a[1]), "r"(a[2]), "r"(a[3]), "r"(b0), "r"(b1));
}
__device__ __forceinline__ uint32_t to_tf32(float v) {
    uint32_t r;
    asm("cvt.rna.tf32.f32 %0, %1;" : "=r"(r) : "f"(v));
    return r;
}
__device__ __forceinline__ void split_tf32(float v, uint32_t& hi, uint32_t& lo) {
    hi = to_tf32(v);
    lo = to_tf32(v - __uint_as_float(hi));
}

// ---- K1: Wt pack only — coalesced loads, scattered stores (measured 5.1us) ----
__global__ void __launch_bounds__(256) prep_k(const float* __restrict__ Wjf,
                                              const float* __restrict__ Wju) {
    int i = blockIdx.x * 256 + threadIdx.x;     // 131072
    int k = i >> 10, j = i & 1023;
    float v = (j < 512) ? Wjf[k * 512 + j] : Wju[k * 512 + j - 512];
    int nt = j >> 7, wn = (j >> 6) & 1, f = (j >> 3) & 7, hi = j & 7;
    int ks = k >> 3, r = (k >> 2) & 1, la = k & 3;
    int lane = hi * 4 + la;
    int dest = (nt << 14) | (ks << 10) | (wn << 9) | (lane << 4) | (f << 1) | r;
    d_Wt[dest] = __uint_as_float(to_tf32(v));
}

// ---- K2: MEGA kernel — gc+nodelin+flv+flag+gemm+einsum+bp, one CTA per graph ----
// alias region (inside s_dat, dead by phase 3):
//   s_ef 0(17424) | s_W 17424(4096) | s_fl 21520(4224) | s_Wc 25744(64)
//   s_gc 25808(1056) | s_gf 26864(64) | s_xn 26928(1536)
// persistent: s_dat 0(46080) | sA 46080 | sB | uA | uB (4x2112) |
//   s_mm 54528 | s_um 54720 | s_if 54912 | s_iu 55104 | s_act 55296(132i) | s_np 55428
#define MEGA_SMEM (55432 * 4)
__global__ void __launch_bounds__(512, 1) mega_k(
        const float* __restrict__ ef, const float* __restrict__ Wfl,
        const float* __restrict__ noise, const float* __restrict__ Wc,
        const float* __restrict__ bc,
        const float* __restrict__ Wjf, const float* __restrict__ bjf,
        const float* __restrict__ Wju, const float* __restrict__ bju,
        const float* __restrict__ bfl, const float* __restrict__ gf,
        const float* __restrict__ nf,
        const float* __restrict__ Wif, const float* __restrict__ bif,
        const float* __restrict__ Wiu, const float* __restrict__ biu,
        float* __restrict__ out) {
    extern __shared__ __align__(16) float sm[];
    float* s_ef = sm;
    float* s_W  = sm + 17424;
    float* s_fl = sm + 21520;
    float* s_Wc = sm + 25744;
    float* s_gc = sm + 25808;
    float* s_gf = sm + 26864;
    float* s_xn = sm + 26928;
    float* s_dat = sm;
    float* sA = sm + 46080;
    float* sB = sA + 2112;
    float* uA = sB + 2112;
    float* uB = uA + 2112;
    float* s_mm = sm + 54528;
    float* s_um = sm + 54720;
    float* s_if = sm + 54912;
    float* s_iu = sm + 55104;
    int* s_act = (int*)(sm + 55296);
    int* s_np  = (int*)(sm + 55428);

    int g = blockIdx.x, t = threadIdx.x;
    if (t == 0) *s_np = 0;
    for (int i = t; i < 8448; i += 512) sA[i] = 0.f;   // sA..uB contiguous
    for (int i = t; i < 4224; i += 512) {
        int r = i >> 5, q = i & 31;
        float4 v = *(const float4*)(ef + (g * EPG + r) * 128 + q * 4);
        *(float4*)(s_ef + r * 132 + q * 4) = v;
    }
    for (int i = t; i < 1024; i += 512)
        *(float4*)(s_W + i * 4) = *(const float4*)(Wfl + i * 4);
    if (t < 64) { s_Wc[t] = Wc[t]; s_gf[t] = gf[g * 64 + t]; }
    for (int i = t; i < 1536; i += 512) {
        int node = i >> 7, kk = i & 127;
        s_xn[i] = (kk < 64) ? nf[(g * NPG + node) * 64 + kk] : gf[g * 64 + kk - 64];
    }
    __syncthreads();

    // ---- Phase 0: gc (graph part + bias) and node linears ----
    for (int j = t; j < 1056; j += 512) {
        const float* Wp; int st; float acc;
        if (j < 512)        { Wp = Wjf + 128 * 512 + j;          st = 512; acc = bjf[j]; }
        else if (j < 1024)  { Wp = Wju + 128 * 512 + (j - 512);  st = 512; acc = bju[j - 512]; }
        else                { Wp = Wfl + 128 * 32  + (j - 1024); st = 32;  acc = bfl[j - 1024]; }
#pragma unroll 8
        for (int k = 0; k < 64; ++k) acc += s_gf[k] * Wp[k * st];
        s_gc[j] = acc;
    }
    if (t < 384) {
        int node = t >> 5, lane = t & 31, col = lane & 15;
        const float* W = (lane < 16) ? Wif : Wiu;
        float acc = (lane < 16) ? bif[col] : biu[col];
        const float* xr = s_xn + node * 128;
#pragma unroll 8
        for (int k = 0; k < 128; ++k) acc += xr[k] * W[k * 16 + col];
        int o = node * 16 + col;
        if (lane < 16) { s_if[o] = acc; s_mm[o] = acc; }
        else           { s_iu[o] = acc; s_um[o] = acc; }
    }
    __syncthreads();

    // ---- Phase 1a: fl linear (264 threads: 2/edge x 16 cols) ----
    if (t < 264) {
        int e = t >> 1, co = (t & 1) * 16;
        ull acc[8];
        const float* gb = s_gc + 1024 + co;
#pragma unroll
        for (int c = 0; c < 8; ++c) acc[c] = pk2(gb[c * 2], gb[c * 2 + 1]);
        const float* er = s_ef + e * 132;
#pragma unroll 4
        for (int k = 0; k < 128; ++k) {
            float a = er[k];
            ull aa = pk2(a, a);
            const float4* wr = (const float4*)(s_W + k * 32 + co);
            float4 w0 = wr[0], w1 = wr[1], w2 = wr[2], w3 = wr[3];
            fma2(acc[0], aa, pk2(w0.x, w0.y)); fma2(acc[1], aa, pk2(w0.z, w0.w));
            fma2(acc[2], aa, pk2(w1.x, w1.y)); fma2(acc[3], aa, pk2(w1.z, w1.w));
            fma2(acc[4], aa, pk2(w2.x, w2.y)); fma2(acc[5], aa, pk2(w2.z, w2.w));
            fma2(acc[6], aa, pk2(w3.x, w3.y)); fma2(acc[7], aa, pk2(w3.z, w3.w));
        }
        float* op = s_fl + e * 32 + co;
#pragma unroll
        for (int c = 0; c < 8; ++c) {
            float lo, hi;
            up2(acc[c], lo, hi);
            op[c * 2] = lo; op[c * 2 + 1] = hi;
        }
    }
    __syncthreads();

    // ---- Phase 1b: gumbel flags + pair-ordered active list ----
    if (t < EPG) {
        int e = t, rev = revloc(e);
        const float* pe = s_fl + e * 32;
        const float* pr = s_fl + rev * 32;
        float l0 = bc[0], l1 = bc[1];
#pragma unroll 8
        for (int c = 0; c < 32; ++c) {
            float p = pe[c] * pr[c];
            l0 += p * s_Wc[c * 2];
            l1 += p * s_Wc[c * 2 + 1];
        }
        int ge = g * EPG + e, grev = g * EPG + rev;
        int mn = min(ge, grev);
        float y0 = l0 + noise[2 * mn];
        float y1 = l1 + noise[2 * mn + 1];
        if (y0 >= y1 && e < rev) {
            int q = atomicAdd(s_np, 1);
            s_act[2 * q] = e;
            s_act[2 * q + 1] = rev;
        }
    }
    __syncthreads();
    int npairs = *s_np;
    int cnt = npairs * 2;

    // ---- Phase 2: tf32 GEMM for active edges: fc[slot] = ef[edge] @ W + gc ----
    {
        int lane = t & 31, warp = t >> 5;
        int nt = warp >> 1, wn = warp & 1;
        int nM = (cnt + 31) >> 5;
        float* fcg = d_fc + (size_t)(g * 132) * 1024;
        int la = lane & 3;
        for (int mc = 0; mc < nM; ++mc) {
            float acc[2][8][4];
#pragma unroll
            for (int a = 0; a < 2; ++a)
#pragma unroll
                for (int f = 0; f < 8; ++f)
#pragma unroll
                    for (int j = 0; j < 4; ++j) acc[a][f][j] = 0.f;
            int rb = mc * 32 + (lane >> 2);
            int c1 = cnt - 1;
            const float* A0 = s_ef + s_act[min(rb, c1)] * 132 + la;
            const float* A1 = s_ef + s_act[min(rb + 8, c1)] * 132 + la;
            const float* A2 = s_ef + s_act[min(rb + 16, c1)] * 132 + la;
            const float* A3 = s_ef + s_act[min(rb + 24, c1)] * 132 + la;
            const float4* wt = (const float4*)d_Wt + (((nt * 16) * 2 + wn) * 32 + lane) * 4;
            float4 bq[4];
#pragma unroll
            for (int j = 0; j < 4; ++j) bq[j] = wt[j];
#pragma unroll
            for (int ks = 0; ks < 16; ++ks) {
                uint32_t br[16];
                br[0]  = __float_as_uint(bq[0].x); br[1]  = __float_as_uint(bq[0].y);
                br[2]  = __float_as_uint(bq[0].z); br[3]  = __float_as_uint(bq[0].w);
                br[4]  = __float_as_uint(bq[1].x); br[5]  = __float_as_uint(bq[1].y);
                br[6]  = __float_as_uint(bq[1].z); br[7]  = __float_as_uint(bq[1].w);
                br[8]  = __float_as_uint(bq[2].x); br[9]  = __float_as_uint(bq[2].y);
                br[10] = __float_as_uint(bq[2].z); br[11] = __float_as_uint(bq[2].w);
                br[12] = __float_as_uint(bq[3].x); br[13] = __float_as_uint(bq[3].y);
                br[14] = __float_as_uint(bq[3].z); br[15] = __float_as_uint(bq[3].w);
                if (ks < 15) {
                    const float4* nxt = wt + (ks + 1) * 256;
#pragma unroll
                    for (int j = 0; j < 4; ++j) bq[j] = nxt[j];
                }
                uint32_t a0[4], a1[4];
                a0[0] = to_tf32(A0[ks * 8]);     a0[1] = to_tf32(A1[ks * 8]);
                a0[2] = to_tf32(A0[ks * 8 + 4]); a0[3] = to_tf32(A1[ks * 8 + 4]);
                a1[0] = to_tf32(A2[ks * 8]);     a1[1] = to_tf32(A3[ks * 8]);
                a1[2] = to_tf32(A2[ks * 8 + 4]); a1[3] = to_tf32(A3[ks * 8 + 4]);
#pragma unroll
                for (int f = 0; f < 8; ++f) {
                    mma_tf32(acc[0][f], a0, br[f * 2], br[f * 2 + 1]);
                    mma_tf32(acc[1][f], a1, br[f * 2], br[f * 2 + 1]);
                }
            }
            int gr = lane >> 2, qc = la * 2;
#pragma unroll
            for (int mf = 0; mf < 2; ++mf) {
#pragma unroll
                for (int rr = 0; rr < 2; ++rr) {
                    int slot = mc * 32 + mf * 16 + gr + rr * 8;
                    if (slot < cnt) {
                        float* fcb = fcg + slot * 1024;
#pragma unroll
                        for (int f = 0; f < 8; ++f) {
                            int col = nt * 128 + wn * 64 + f * 8 + qc;
                            float2 gv = *(const float2*)(s_gc + col);
                            float2 ov;
                            ov.x = acc[mf][f][rr * 2 + 0] + gv.x;
                            ov.y = acc[mf][f][rr * 2 + 1] + gv.y;
                            *(float2*)(fcb + col) = ov;
                        }
                    }
                }
            }
        }
    }
    __syncthreads();

    // ---- Phase 3: 3xTF32 einsum per pair -> swizzled smem (spill to gmem, slot-indexed) ----
    {
        int lane = t & 31, warp = t >> 5;
        int r = lane >> 2, cb = lane & 3;
        const float* fcg = d_fc + (size_t)(g * 132) * 1024;
        float* fvg = d_fv + (size_t)(g * 132) * 256;
        float* uvg = d_uv + (size_t)(g * 132) * 256;
        for (int p = warp; p < npairs; p += 16) {
            const float* fe = fcg + (2 * p) * 1024;
            const float* frp = fcg + (2 * p + 1) * 1024;
#pragma unroll
            for (int mat = 0; mat < 2; ++mat) {
                float acc[2][4];
#pragma unroll
                for (int nf = 0; nf < 2; ++nf)
#pragma unroll
                    for (int j = 0; j < 4; ++j) acc[nf][j] = 0.f;
#pragma unroll
                for (int ks = 0; ks < 4; ++ks) {
                    const float* ap = fe + mat * 512 + r * 32 + ks * 8 + cb;
                    float av[4] = {ap[0], ap[256], ap[4], ap[260]};
                    uint32_t ah[4], al[4];
#pragma unroll
                    for (int j = 0; j < 4; ++j) split_tf32(av[j], ah[j], al[j]);
#pragma unroll
                    for (int nf = 0; nf < 2; ++nf) {
                        const float* bp_ = frp + mat * 512 + (nf * 8 + r) * 32 + ks * 8 + cb;
                        float b0f = bp_[0], b1f = bp_[4];
                        uint32_t bh0, bl0, bh1, bl1;
                        split_tf32(b0f, bh0, bl0);
                        split_tf32(b1f, bh1, bl1);
                        mma_tf32(acc[nf], ah, bh0, bh1);
                        mma_tf32(acc[nf], ah, bl0, bl1);
                        mma_tf32(acc[nf], al, bh0, bh1);
                    }
                }
                float* gme = (mat ? uvg : fvg);
                int se = 2 * p, sr = 2 * p + 1;
#pragma unroll
                for (int nf = 0; nf < 2; ++nf) {
                    int b = nf * 8 + cb * 2;
                    int r8 = r + 8;
                    if (se < CAP) {
                        float* db = s_dat + se * 512 + mat * 256;
                        db[(r * 4 + ((b >> 2) ^ (r >> 2))) * 4 + (b & 3)] = acc[nf][0];
                        db[(r * 4 + (((b + 1) >> 2) ^ (r >> 2))) * 4 + ((b + 1) & 3)] = acc[nf][1];
                        db[(r8 * 4 + ((b >> 2) ^ (r8 >> 2))) * 4 + (b & 3)] = acc[nf][2];
                        db[(r8 * 4 + (((b + 1) >> 2) ^ (r8 >> 2))) * 4 + ((b + 1) & 3)] = acc[nf][3];
                    } else {
                        float* gp = gme + se * 256;
                        gp[r * 16 + b] = acc[nf][0];
                        gp[r * 16 + b + 1] = acc[nf][1];
                        gp[r8 * 16 + b] = acc[nf][2];
                        gp[r8 * 16 + b + 1] = acc[nf][3];
                    }
                    if (sr < CAP) {
                        float* db = s_dat + sr * 512 + mat * 256;
                        db[(b * 4 + ((r >> 2) ^ (b >> 2))) * 4 + (r & 3)] = acc[nf][0];
                        db[((b + 1) * 4 + ((r >> 2) ^ ((b + 1) >> 2))) * 4 + (r & 3)] = acc[nf][1];
                        db[(b * 4 + ((r8 >> 2) ^ (b >> 2))) * 4 + (r8 & 3)] = acc[nf][2];
                        db[((b + 1) * 4 + ((r8 >> 2) ^ ((b + 1) >> 2))) * 4 + (r8 & 3)] = acc[nf][3];
                    } else {
                        float* gp = gme + sr * 256;
                        gp[b * 16 + r] = acc[nf][0];
                        gp[(b + 1) * 16 + r] = acc[nf][1];
                        gp[b * 16 + r8] = acc[nf][2];
                        gp[(b + 1) * 16 + r8] = acc[nf][3];
                    }
                }
            }
        }
    }
    __syncthreads();

    // ---- Phase 4: BP iterations ----
    {
        const float* fvg = d_fv + (size_t)(g * 132) * 256;
        const float* uvg = d_uv + (size_t)(g * 132) * 256;
        int cnt16 = cnt * 16;
        for (int it = 0; it < NPG; ++it) {
            const float* om = (it & 1) ? sB : sA;
            const float* ou = (it & 1) ? uB : uA;
            float* nm = (it & 1) ? sA : sB;
            float* nu = (it & 1) ? uA : uB;
            for (int idx = t; idx < cnt16; idx += 512) {
                int p = idx >> 4;
                int e = s_act[p];
                int a = idx & 15;
                unsigned mask = (t & 16) ? 0xFFFF0000u : 0x0000FFFFu;
                int s = e / 11;
                int rev = revloc(e);
                float4 f0, f1, f2, f3, u0, u1, u2, u3;
                if (p < CAP) {
                    const float* db = s_dat + p * 512;
                    int ax4 = a * 4, ash = a >> 2;
                    f0 = *(const float4*)(db + (ax4 + (0 ^ ash)) * 4);
                    f1 = *(const float4*)(db + (ax4 + (1 ^ ash)) * 4);
                    f2 = *(const float4*)(db + (ax4 + (2 ^ ash)) * 4);
                    f3 = *(const float4*)(db + (ax4 + (3 ^ ash)) * 4);
                    const float* ub = db + 256;
                    u0 = *(const float4*)(ub + (ax4 + (0 ^ ash)) * 4);
                    u1 = *(const float4*)(ub + (ax4 + (1 ^ ash)) * 4);
                    u2 = *(const float4*)(ub + (ax4 + (2 ^ ash)) * 4);
                    u3 = *(const float4*)(ub + (ax4 + (3 ^ ash)) * 4);
                } else {
                    const float4* fvp = (const float4*)(fvg + p * 256 + a * 16);
                    const float4* uvp = (const float4*)(uvg + p * 256 + a * 16);
                    f0 = fvp[0]; f1 = fvp[1]; f2 = fvp[2]; f3 = fvp[3];
                    u0 = uvp[0]; u1 = uvp[1]; u2 = uvp[2]; u3 = uvp[3];
                }
                float fv[16] = {f0.x, f0.y, f0.z, f0.w, f1.x, f1.y, f1.z, f1.w,
                                f2.x, f2.y, f2.z, f2.w, f3.x, f3.y, f3.z, f3.w};
                float uv[16] = {u0.x, u0.y, u0.z, u0.w, u1.x, u1.y, u1.z, u1.w,
                                u2.x, u2.y, u2.z, u2.w, u3.x, u3.y, u3.z, u3.w};
                float m[16], mx = -1e30f;
#pragma unroll
                for (int b = 0; b < 16; ++b) {
                    float agg = s_mm[s * 16 + b] - om[rev * 16 + b];
                    m[b] = fv[b] + agg;
                    mx = fmaxf(mx, m[b]);
                }
                float se = 0.f;
#pragma unroll
                for (int b = 0; b < 16; ++b) {
                    float pb = __expf(m[b] - mx);
                    m[b] = pb;
                    se += pb;
                }
                float lse = mx + __logf(se);
                float ssum = lse;
#pragma unroll
                for (int w = 8; w > 0; w >>= 1) ssum += __shfl_xor_sync(mask, ssum, w);
                nm[e * 16 + a] = lse - ssum * 0.0625f;
                float acc = 0.f;
#pragma unroll
                for (int b = 0; b < 16; ++b) {
                    float util = s_um[s * 16 + b] - ou[rev * 16 + b];
                    acc += (uv[b] + util) * m[b];
                }
                nu[e * 16 + a] = acc * __fdividef(1.f, se);
            }
            __syncthreads();
            if (t < 192) {
                int n = t >> 4, b = t & 15;
                float am = 0.f, au = 0.f;
#pragma unroll
                for (int s2 = 0; s2 < NPG; ++s2) {
                    if (s2 == n) continue;
                    int ee = s2 * 11 + n - (n > s2);
                    am += nm[ee * 16 + b];
                    au += nu[ee * 16 + b];
                }
                s_mm[t] = am + s_if[t];
                s_um[t] = au + s_iu[t];
            }
            __syncthreads();
        }
    }
    if (t < 16) out[g * 16 + t] = s_um[t];
}

extern "C" void kernel_launch(void* const* d_in, const int* in_sizes, int n_in,
                              void* d_out, int out_size) {
    const float* ef   = (const float*)d_in[0];
    const float* nf   = (const float*)d_in[1];
    const float* gf   = (const float*)d_in[2];
    const float* gn   = (const float*)d_in[7];
    const float* Wjf  = (const float*)d_in[8];
    const float* bjf  = (const float*)d_in[9];
    const float* Wif  = (const float*)d_in[10];
    const float* bif  = (const float*)d_in[11];
    const float* Wju  = (const float*)d_in[12];
    const float* bju  = (const float*)d_in[13];
    const float* Wiu  = (const float*)d_in[14];
    const float* biu  = (const float*)d_in[15];
    const float* Wfl  = (const float*)d_in[16];
    const float* bfl  = (const float*)d_in[17];
    const float* Wcls = (const float*)d_in[18];
    const float* bcls = (const float*)d_in[19];
    float* out = (float*)d_out;

    static int attr_set = 0;
    if (!attr_set) {
        cudaFuncSetAttribute(mega_k, cudaFuncAttributeMaxDynamicSharedMemorySize, MEGA_SMEM);
        attr_set = 1;
    }

    prep_k<<<512, 256>>>(Wjf, Wju);
    mega_k<<<B_, 512, MEGA_SMEM>>>(ef, Wfl, gn, Wcls, bcls,
                                   Wjf, bjf, Wju, bju, bfl, gf,
                                   nf, Wif, bif, Wiu, biu, out);
}

// round 17
// speedup vs baseline: 1.9491x; 1.7638x over previous
#include <cuda_runtime.h>
#include <cstdint>

#define B_    128
#define NPG   12
#define EPG   132
#define E_TOT 16896
#define NT    1536
#define NC    1056   // 512 jf | 512 ju | 32 fl (in d_gc)
#define CAP   90

__device__ float d_Wt[131072];         // tf32-prerounded, fragment-swizzled
__device__ float d_gc[B_ * NC];
__device__ float d_fc[E_TOT * 1024];   // slot-compacted per graph: (g*132+slot)*1024
__device__ float d_fv[E_TOT * 256];    // spill only (slot-indexed)
__device__ float d_uv[E_TOT * 256];
__device__ float d_if[NT * 16];
__device__ float d_iu[NT * 16];

__device__ __forceinline__ unsigned long long pk2(float lo, float hi) {
    unsigned long long r;
    asm("mov.b64 %0, {%1, %2};" : "=l"(r) : "f"(lo), "f"(hi));
    return r;
}
__device__ __forceinline__ void fma2(unsigned long long& d, unsigned long long a, unsigned long long b) {
    asm("fma.rn.f32x2 %0, %1, %2, %0;" : "+l"(d) : "l"(a), "l"(b));
}
__device__ __forceinline__ void up2(unsigned long long v, float& lo, float& hi) {
    asm("mov.b64 {%0, %1}, %2;" : "=f"(lo), "=f"(hi) : "l"(v));
}
__device__ __forceinline__ int revloc(int ee) {
    int s = ee / 11, dd = ee - s * 11;
    int d = dd + (dd >= s);
    return d * 11 + s - (s > d);
}
__device__ __forceinline__ void mma_tf32(float* d, const uint32_t* a, uint32_t b0, uint32_t b1) {
    asm volatile("mma.sync.aligned.m16n8k8.row.col.f32.tf32.tf32.f32 "
        "{%0,%1,%2,%3}, {%4,%5,%6,%7}, {%8,%9}, {%0,%1,%2,%3};\n"
        : "+f"(d[0]), "+f"(d[1]), "+f"(d[2]), "+f"(d[3])
        : "r"(a[0]), "r"(a[1]), "r"(a[2]), "r"(a[3]), "r"(b0), "r"(b1));
}
__device__ __forceinline__ uint32_t to_tf32(float v) {
    uint32_t r;
    asm("cvt.rna.tf32.f32 %0, %1;" : "=r"(r) : "f"(v));
    return r;
}
__device__ __forceinline__ void split_tf32(float v, uint32_t& hi, uint32_t& lo) {
    hi = to_tf32(v);
    lo = to_tf32(v - __uint_as_float(hi));
}

// ---- K1: fused prep: Wt pack COALESCED (blocks 0..511) | gc (512..1039) | node lin (1040..1231) ----
__global__ void __launch_bounds__(256) prep_k(
        const float* __restrict__ Wjf, const float* __restrict__ bjf,
        const float* __restrict__ Wju, const float* __restrict__ bju,
        const float* __restrict__ Wfl, const float* __restrict__ bfl,
        const float* __restrict__ gf,  const float* __restrict__ nf,
        const float* __restrict__ Wif, const float* __restrict__ bif,
        const float* __restrict__ Wiu, const float* __restrict__ biu) {
    __shared__ float xn[8][128];
    int b = blockIdx.x, t = threadIdx.x;
    if (b < 512) {
        // coalesced loads, scattered stores (verified identical layout to fragment order)
        int i = b * 256 + t;                 // 131072
        int k = i >> 10, j = i & 1023;
        float v = (j < 512) ? Wjf[k * 512 + j] : Wju[k * 512 + j - 512];
        int nt = j >> 7, wn = (j >> 6) & 1, f = (j >> 3) & 7, hi = j & 7;
        int ks = k >> 3, r = (k >> 2) & 1, la = k & 3;
        int lane = hi * 4 + la;
        int dest = (nt << 14) | (ks << 10) | (wn << 9) | (lane << 4) | (f << 1) | r;
        d_Wt[dest] = __uint_as_float(to_tf32(v));
    } else if (b < 1040) {
        int i = (b - 512) * 256 + t;
        int g = i / NC, j = i - g * NC;
        const float* Wp; int st; float acc;
        if (j < 512)        { Wp = Wjf + 128 * 512 + j;          st = 512; acc = bjf[j]; }
        else if (j < 1024)  { Wp = Wju + 128 * 512 + (j - 512);  st = 512; acc = bju[j - 512]; }
        else                { Wp = Wfl + 128 * 32  + (j - 1024); st = 32;  acc = bfl[j - 1024]; }
        const float* gr = gf + g * 64;
#pragma unroll 8
        for (int k = 0; k < 64; ++k) acc += gr[k] * Wp[k * st];
        d_gc[i] = acc;
    } else {
        int nb = (b - 1040) * 8;
        for (int i = t; i < 1024; i += 256) {
            int node = i >> 7, kk = i & 127;
            xn[node][kk] = (kk < 64) ? nf[(nb + node) * 64 + kk]
                                     : gf[((nb + node) / NPG) * 64 + kk - 64];
        }
        __syncthreads();
        int w = t >> 5, lane = t & 31;
        int n = nb + w;
        const float* W = (lane < 16) ? Wif : Wiu;
        int col = lane & 15;
        float acc = (lane < 16) ? bif[col] : biu[col];
#pragma unroll 8
        for (int k = 0; k < 128; ++k) acc += xn[w][k] * W[k * 16 + col];
        if (lane < 16) d_if[n * 16 + col] = acc;
        else           d_iu[n * 16 + col] = acc;
    }
}

// ---- K2: MEGA kernel — one CTA per graph does flv+flag+gemm+einsum+bp ----
#define MEGA_SMEM (55432 * 4)
__global__ void __launch_bounds__(512, 1) mega_k(
        const float* __restrict__ ef, const float* __restrict__ Wfl,
        const float* __restrict__ noise, const float* __restrict__ Wc,
        const float* __restrict__ bc, float* __restrict__ out) {
    extern __shared__ __align__(16) float sm[];
    float* s_ef = sm;
    float* s_W  = sm + 17424;
    float* s_fl = sm + 21520;
    float* s_Wc = sm + 25744;
    float* s_dat = sm;
    float* sA = sm + 46080;
    float* sB = sA + 2112;
    float* uA = sB + 2112;
    float* uB = uA + 2112;
    float* s_mm = sm + 54528;
    float* s_um = sm + 54720;
    float* s_if = sm + 54912;
    float* s_iu = sm + 55104;
    int* s_act = (int*)(sm + 55296);
    int* s_np  = (int*)(sm + 55428);

    int g = blockIdx.x, t = threadIdx.x;
    if (t == 0) *s_np = 0;
    for (int i = t; i < 8448; i += 512) sA[i] = 0.f;
    if (t < 192) {
        float fi = d_if[g * 192 + t], ui = d_iu[g * 192 + t];
        s_if[t] = fi; s_iu[t] = ui;
        s_mm[t] = fi; s_um[t] = ui;
    }
    for (int i = t; i < 4224; i += 512) {
        int r = i >> 5, q = i & 31;
        float4 v = *(const float4*)(ef + (g * EPG + r) * 128 + q * 4);
        *(float4*)(s_ef + r * 132 + q * 4) = v;
    }
    for (int i = t; i < 1024; i += 512)
        *(float4*)(s_W + i * 4) = *(const float4*)(Wfl + i * 4);
    if (t < 64) s_Wc[t] = Wc[t];
    __syncthreads();

    // ---- Phase 1a: fl linear (264 threads: 2/edge x 16 cols) ----
    if (t < 264) {
        int e = t >> 1, co = (t & 1) * 16;
        unsigned long long acc[8];
        const float* gb = d_gc + g * NC + 1024 + co;
#pragma unroll
        for (int c = 0; c < 8; ++c) acc[c] = pk2(gb[c * 2], gb[c * 2 + 1]);
        const float* er = s_ef + e * 132;
#pragma unroll 4
        for (int k = 0; k < 128; ++k) {
            float a = er[k];
            unsigned long long aa = pk2(a, a);
            const float4* wr = (const float4*)(s_W + k * 32 + co);
            float4 w0 = wr[0], w1 = wr[1], w2 = wr[2], w3 = wr[3];
            fma2(acc[0], aa, pk2(w0.x, w0.y)); fma2(acc[1], aa, pk2(w0.z, w0.w));
            fma2(acc[2], aa, pk2(w1.x, w1.y)); fma2(acc[3], aa, pk2(w1.z, w1.w));
            fma2(acc[4], aa, pk2(w2.x, w2.y)); fma2(acc[5], aa, pk2(w2.z, w2.w));
            fma2(acc[6], aa, pk2(w3.x, w3.y)); fma2(acc[7], aa, pk2(w3.z, w3.w));
        }
        float* op = s_fl + e * 32 + co;
#pragma unroll
        for (int c = 0; c < 8; ++c) {
            float lo, hi;
            up2(acc[c], lo, hi);
            op[c * 2] = lo; op[c * 2 + 1] = hi;
        }
    }
    __syncthreads();

    // ---- Phase 1b: gumbel flags + pair-ordered active list ----
    if (t < EPG) {
        int e = t, rev = revloc(e);
        const float* pe = s_fl + e * 32;
        const float* pr = s_fl + rev * 32;
        float l0 = bc[0], l1 = bc[1];
#pragma unroll 8
        for (int c = 0; c < 32; ++c) {
            float p = pe[c] * pr[c];
            l0 += p * s_Wc[c * 2];
            l1 += p * s_Wc[c * 2 + 1];
        }
        int ge = g * EPG + e, grev = g * EPG + rev;
        int mn = min(ge, grev);
        float y0 = l0 + noise[2 * mn];
        float y1 = l1 + noise[2 * mn + 1];
        if (y0 >= y1 && e < rev) {
            int q = atomicAdd(s_np, 1);
            s_act[2 * q] = e;
            s_act[2 * q + 1] = rev;
        }
    }
    __syncthreads();
    int npairs = *s_np;
    int cnt = npairs * 2;

    // ---- Phase 2: tf32 GEMM for active edges: fc[slot] = ef[edge] @ W + gc ----
    {
        int lane = t & 31, warp = t >> 5;
        int nt = warp >> 1, wn = warp & 1;
        int nM = (cnt + 31) >> 5;
        const float* gcb = d_gc + g * NC;
        float* fcg = d_fc + (size_t)(g * 132) * 1024;
        int la = lane & 3;
        for (int mc = 0; mc < nM; ++mc) {
            float acc[2][8][4];
#pragma unroll
            for (int a = 0; a < 2; ++a)
#pragma unroll
                for (int f = 0; f < 8; ++f)
#pragma unroll
                    for (int j = 0; j < 4; ++j) acc[a][f][j] = 0.f;
            int rb = mc * 32 + (lane >> 2);
            int c1 = cnt - 1;
            const float* A0 = s_ef + s_act[min(rb, c1)] * 132 + la;
            const float* A1 = s_ef + s_act[min(rb + 8, c1)] * 132 + la;
            const float* A2 = s_ef + s_act[min(rb + 16, c1)] * 132 + la;
            const float* A3 = s_ef + s_act[min(rb + 24, c1)] * 132 + la;
            const float4* wt = (const float4*)d_Wt + (((nt * 16) * 2 + wn) * 32 + lane) * 4;
            float4 bq[4];
#pragma unroll
            for (int j = 0; j < 4; ++j) bq[j] = wt[j];
#pragma unroll
            for (int ks = 0; ks < 16; ++ks) {
                uint32_t br[16];
                br[0]  = __float_as_uint(bq[0].x); br[1]  = __float_as_uint(bq[0].y);
                br[2]  = __float_as_uint(bq[0].z); br[3]  = __float_as_uint(bq[0].w);
                br[4]  = __float_as_uint(bq[1].x); br[5]  = __float_as_uint(bq[1].y);
                br[6]  = __float_as_uint(bq[1].z); br[7]  = __float_as_uint(bq[1].w);
                br[8]  = __float_as_uint(bq[2].x); br[9]  = __float_as_uint(bq[2].y);
                br[10] = __float_as_uint(bq[2].z); br[11] = __float_as_uint(bq[2].w);
                br[12] = __float_as_uint(bq[3].x); br[13] = __float_as_uint(bq[3].y);
                br[14] = __float_as_uint(bq[3].z); br[15] = __float_as_uint(bq[3].w);
                if (ks < 15) {
                    const float4* nxt = wt + (ks + 1) * 256;
#pragma unroll
                    for (int j = 0; j < 4; ++j) bq[j] = nxt[j];
                }
                uint32_t a0[4], a1[4];
                a0[0] = to_tf32(A0[ks * 8]);     a0[1] = to_tf32(A1[ks * 8]);
                a0[2] = to_tf32(A0[ks * 8 + 4]); a0[3] = to_tf32(A1[ks * 8 + 4]);
                a1[0] = to_tf32(A2[ks * 8]);     a1[1] = to_tf32(A3[ks * 8]);
                a1[2] = to_tf32(A2[ks * 8 + 4]); a1[3] = to_tf32(A3[ks * 8 + 4]);
#pragma unroll
                for (int f = 0; f < 8; ++f) {
                    mma_tf32(acc[0][f], a0, br[f * 2], br[f * 2 + 1]);
                    mma_tf32(acc[1][f], a1, br[f * 2], br[f * 2 + 1]);
                }
            }
            int gr = lane >> 2, qc = la * 2;
#pragma unroll
            for (int mf = 0; mf < 2; ++mf) {
#pragma unroll
                for (int rr = 0; rr < 2; ++rr) {
                    int slot = mc * 32 + mf * 16 + gr + rr * 8;
                    if (slot < cnt) {
                        float* fcb = fcg + slot * 1024;
#pragma unroll
                        for (int f = 0; f < 8; ++f) {
                            int col = nt * 128 + wn * 64 + f * 8 + qc;
                            float2 gv = *(const float2*)(gcb + col);
                            float2 ov;
                            ov.x = acc[mf][f][rr * 2 + 0] + gv.x;
                            ov.y = acc[mf][f][rr * 2 + 1] + gv.y;
                            *(float2*)(fcb + col) = ov;
                        }
                    }
                }
            }
        }
    }
    __syncthreads();

    // ---- Phase 3: 3xTF32 einsum per pair -> swizzled smem (spill to gmem, slot-indexed) ----
    {
        int lane = t & 31, warp = t >> 5;
        int r = lane >> 2, cb = lane & 3;
        const float* fcg = d_fc + (size_t)(g * 132) * 1024;
        float* fvg = d_fv + (size_t)(g * 132) * 256;
        float* uvg = d_uv + (size_t)(g * 132) * 256;
        for (int p = warp; p < npairs; p += 16) {
            const float* fe = fcg + (2 * p) * 1024;
            const float* frp = fcg + (2 * p + 1) * 1024;
#pragma unroll
            for (int mat = 0; mat < 2; ++mat) {
                float acc[2][4];
#pragma unroll
                for (int nf = 0; nf < 2; ++nf)
#pragma unroll
                    for (int j = 0; j < 4; ++j) acc[nf][j] = 0.f;
#pragma unroll
                for (int ks = 0; ks < 4; ++ks) {
                    const float* ap = fe + mat * 512 + r * 32 + ks * 8 + cb;
                    float av[4] = {ap[0], ap[256], ap[4], ap[260]};
                    uint32_t ah[4], al[4];
#pragma unroll
                    for (int j = 0; j < 4; ++j) split_tf32(av[j], ah[j], al[j]);
#pragma unroll
                    for (int nf = 0; nf < 2; ++nf) {
                        const float* bp_ = frp + mat * 512 + (nf * 8 + r) * 32 + ks * 8 + cb;
                        float b0f = bp_[0], b1f = bp_[4];
                        uint32_t bh0, bl0, bh1, bl1;
                        split_tf32(b0f, bh0, bl0);
                        split_tf32(b1f, bh1, bl1);
                        mma_tf32(acc[nf], ah, bh0, bh1);
                        mma_tf32(acc[nf], ah, bl0, bl1);
                        mma_tf32(acc[nf], al, bh0, bh1);
                    }
                }
                float* gme = (mat ? uvg : fvg);
                int se = 2 * p, sr = 2 * p + 1;
#pragma unroll
                for (int nf = 0; nf < 2; ++nf) {
                    int b = nf * 8 + cb * 2;
                    int r8 = r + 8;
                    if (se < CAP) {
                        float* db = s_dat + se * 512 + mat * 256;
                        db[(r * 4 + ((b >> 2) ^ (r >> 2))) * 4 + (b & 3)] = acc[nf][0];
                        db[(r * 4 + (((b + 1) >> 2) ^ (r >> 2))) * 4 + ((b + 1) & 3)] = acc[nf][1];
                        db[(r8 * 4 + ((b >> 2) ^ (r8 >> 2))) * 4 + (b & 3)] = acc[nf][2];
                        db[(r8 * 4 + (((b + 1) >> 2) ^ (r8 >> 2))) * 4 + ((b + 1) & 3)] = acc[nf][3];
                    } else {
                        float* gp = gme + se * 256;
                        gp[r * 16 + b] = acc[nf][0];
                        gp[r * 16 + b + 1] = acc[nf][1];
                        gp[r8 * 16 + b] = acc[nf][2];
                        gp[r8 * 16 + b + 1] = acc[nf][3];
                    }
                    if (sr < CAP) {
                        float* db = s_dat + sr * 512 + mat * 256;
                        db[(b * 4 + ((r >> 2) ^ (b >> 2))) * 4 + (r & 3)] = acc[nf][0];
                        db[((b + 1) * 4 + ((r >> 2) ^ ((b + 1) >> 2))) * 4 + (r & 3)] = acc[nf][1];
                        db[(b * 4 + ((r8 >> 2) ^ (b >> 2))) * 4 + (r8 & 3)] = acc[nf][2];
                        db[((b + 1) * 4 + ((r8 >> 2) ^ ((b + 1) >> 2))) * 4 + (r8 & 3)] = acc[nf][3];
                    } else {
                        float* gp = gme + sr * 256;
                        gp[b * 16 + r] = acc[nf][0];
                        gp[(b + 1) * 16 + r] = acc[nf][1];
                        gp[b * 16 + r8] = acc[nf][2];
                        gp[(b + 1) * 16 + r8] = acc[nf][3];
                    }
                }
            }
        }
    }
    __syncthreads();

    // ---- Phase 4: BP iterations ----
    {
        const float* fvg = d_fv + (size_t)(g * 132) * 256;
        const float* uvg = d_uv + (size_t)(g * 132) * 256;
        int cnt16 = cnt * 16;
        for (int it = 0; it < NPG; ++it) {
            const float* om = (it & 1) ? sB : sA;
            const float* ou = (it & 1) ? uB : uA;
            float* nm = (it & 1) ? sA : sB;
            float* nu = (it & 1) ? uA : uB;
            for (int idx = t; idx < cnt16; idx += 512) {
                int p = idx >> 4;
                int e = s_act[p];
                int a = idx & 15;
                unsigned mask = (t & 16) ? 0xFFFF0000u : 0x0000FFFFu;
                int s = e / 11;
                int rev = revloc(e);
                float4 f0, f1, f2, f3, u0, u1, u2, u3;
                if (p < CAP) {
                    const float* db = s_dat + p * 512;
                    int ax4 = a * 4, ash = a >> 2;
                    f0 = *(const float4*)(db + (ax4 + (0 ^ ash)) * 4);
                    f1 = *(const float4*)(db + (ax4 + (1 ^ ash)) * 4);
                    f2 = *(const float4*)(db + (ax4 + (2 ^ ash)) * 4);
                    f3 = *(const float4*)(db + (ax4 + (3 ^ ash)) * 4);
                    const float* ub = db + 256;
                    u0 = *(const float4*)(ub + (ax4 + (0 ^ ash)) * 4);
                    u1 = *(const float4*)(ub + (ax4 + (1 ^ ash)) * 4);
                    u2 = *(const float4*)(ub + (ax4 + (2 ^ ash)) * 4);
                    u3 = *(const float4*)(ub + (ax4 + (3 ^ ash)) * 4);
                } else {
                    const float4* fvp = (const float4*)(fvg + p * 256 + a * 16);
                    const float4* uvp = (const float4*)(uvg + p * 256 + a * 16);
                    f0 = fvp[0]; f1 = fvp[1]; f2 = fvp[2]; f3 = fvp[3];
                    u0 = uvp[0]; u1 = uvp[1]; u2 = uvp[2]; u3 = uvp[3];
                }
                float fv[16] = {f0.x, f0.y, f0.z, f0.w, f1.x, f1.y, f1.z, f1.w,
                                f2.x, f2.y, f2.z, f2.w, f3.x, f3.y, f3.z, f3.w};
                float uv[16] = {u0.x, u0.y, u0.z, u0.w, u1.x, u1.y, u1.z, u1.w,
                                u2.x, u2.y, u2.z, u2.w, u3.x, u3.y, u3.z, u3.w};
                float m[16], mx = -1e30f;
#pragma unroll
                for (int b = 0; b < 16; ++b) {
                    float agg = s_mm[s * 16 + b] - om[rev * 16 + b];
                    m[b] = fv[b] + agg;
                    mx = fmaxf(mx, m[b]);
                }
                float se = 0.f;
#pragma unroll
                for (int b = 0; b < 16; ++b) {
                    float pb = __expf(m[b] - mx);
                    m[b] = pb;
                    se += pb;
                }
                float lse = mx + __logf(se);
                float ssum = lse;
#pragma unroll
                for (int w = 8; w > 0; w >>= 1) ssum += __shfl_xor_sync(mask, ssum, w);
                nm[e * 16 + a] = lse - ssum * 0.0625f;
                float acc = 0.f;
#pragma unroll
                for (int b = 0; b < 16; ++b) {
                    float util = s_um[s * 16 + b] - ou[rev * 16 + b];
                    acc += (uv[b] + util) * m[b];
                }
                nu[e * 16 + a] = acc * __fdividef(1.f, se);
            }
            __syncthreads();
            if (t < 192) {
                int n = t >> 4, b = t & 15;
                float am = 0.f, au = 0.f;
#pragma unroll
                for (int s2 = 0; s2 < NPG; ++s2) {
                    if (s2 == n) continue;
                    int ee = s2 * 11 + n - (n > s2);
                    am += nm[ee * 16 + b];
                    au += nu[ee * 16 + b];
                }
                s_mm[t] = am + s_if[t];
                s_um[t] = au + s_iu[t];
            }
            __syncthreads();
        }
    }
    if (t < 16) out[g * 16 + t] = s_um[t];
}

extern "C" void kernel_launch(void* const* d_in, const int* in_sizes, int n_in,
                              void* d_out, int out_size) {
    const float* ef   = (const float*)d_in[0];
    const float* nf   = (const float*)d_in[1];
    const float* gf   = (const float*)d_in[2];
    const float* gn   = (const float*)d_in[7];
    const float* Wjf  = (const float*)d_in[8];
    const float* bjf  = (const float*)d_in[9];
    const float* Wif  = (const float*)d_in[10];
    const float* bif  = (const float*)d_in[11];
    const float* Wju  = (const float*)d_in[12];
    const float* bju  = (const float*)d_in[13];
    const float* Wiu  = (const float*)d_in[14];
    const float* biu  = (const float*)d_in[15];
    const float* Wfl  = (const float*)d_in[16];
    const float* bfl  = (const float*)d_in[17];
    const float* Wcls = (const float*)d_in[18];
    const float* bcls = (const float*)d_in[19];
    float* out = (float*)d_out;

    static int attr_set = 0;
    if (!attr_set) {
        cudaFuncSetAttribute(mega_k, cudaFuncAttributeMaxDynamicSharedMemorySize, MEGA_SMEM);
        attr_set = 1;
    }

    prep_k<<<1232, 256>>>(Wjf, bjf, Wju, bju, Wfl, bfl, gf, nf, Wif, bif, Wiu, biu);
    mega_k<<<B_, 512, MEGA_SMEM>>>(ef, Wfl, gn, Wcls, bcls, out);
}